// round 5
// baseline (speedup 1.0000x reference)
#include <cuda_runtime.h>
#include <math.h>
#include <stdint.h>

#define BATCH 2
#define SEQ   2048
#define DMODEL 1024
#define HEADS 16
#define HD    64
#define QKV_N (3*DMODEL)       // 3072
#define MROWS (BATCH*SEQ)      // 4096

__device__ float g_qkv[(size_t)MROWS * QKV_N];    // [B*S, 3072]
__device__ float g_att[(size_t)MROWS * DMODEL];   // [B*S, 1024]

// ===========================================================================
// helpers
// ===========================================================================
__device__ __forceinline__ float f2tf32(float f) {
    uint32_t r;
    asm("cvt.rna.tf32.f32 %0, %1;" : "=r"(r) : "f"(f));
    return __uint_as_float(r);
}

__device__ __forceinline__ uint32_t smem_u32(const void* p) {
    uint32_t a;
    asm("{ .reg .u64 t; cvta.to.shared.u64 t, %1; cvt.u32.u64 %0, t; }" : "=r"(a) : "l"(p));
    return a;
}

__device__ __forceinline__ void mma_tf32(float c[4], const uint32_t a[4], const uint32_t b[2]) {
    asm volatile(
        "mma.sync.aligned.m16n8k8.row.col.f32.tf32.tf32.f32 "
        "{%0,%1,%2,%3}, {%4,%5,%6,%7}, {%8,%9}, {%0,%1,%2,%3};"
        : "+f"(c[0]), "+f"(c[1]), "+f"(c[2]), "+f"(c[3])
        : "r"(a[0]), "r"(a[1]), "r"(a[2]), "r"(a[3]), "r"(b[0]), "r"(b[1]));
}

// one ldmatrix.x4: loads 4 8x8-b16 (= 8x4-tf32) tiles; thread l supplies the
// row address for (matrix l>>3, row l&7).
__device__ __forceinline__ void ldsm_x4(uint32_t r[4], uint32_t saddr) {
    asm volatile("ldmatrix.sync.aligned.m8n8.x4.shared.b16 {%0,%1,%2,%3}, [%4];"
                 : "=r"(r[0]), "=r"(r[1]), "=r"(r[2]), "=r"(r[3]) : "r"(saddr));
}

// ===========================================================================
// tf32 mma.sync GEMM + bias:  C[M,N] = A[M,K] @ W[K,N] + bias[N]
// 128x128 CTA, BK=16, 8 warps (64x32 each). A-frags via ldmatrix.x4.
// ===========================================================================
#define AS_P 20
#define BS_P 136
#define AS_FLOATS (128 * AS_P)
#define BS_FLOATS (16 * BS_P)
#define GEMM_SMEM ((2 * AS_FLOATS + 2 * BS_FLOATS) * sizeof(float))

__global__ __launch_bounds__(256)
void gemm_mma_kernel(const float* __restrict__ A, const float* __restrict__ W,
                     const float* __restrict__ bias, float* __restrict__ C,
                     int N, int K)
{
    extern __shared__ float smf[];
    float* As[2] = { smf, smf + AS_FLOATS };
    float* Bs[2] = { smf + 2 * AS_FLOATS, smf + 2 * AS_FLOATS + BS_FLOATS };

    const int t    = threadIdx.x;
    const int lane = t & 31;
    const int wid  = t >> 5;
    const int wm   = (wid >> 2) * 64;
    const int wn   = (wid & 3) * 32;
    const int g    = lane >> 2;
    const int t4   = lane & 3;
    const int m0   = blockIdx.y * 128;
    const int n0   = blockIdx.x * 128;

    // ldmatrix per-lane offset for A-frags (row-major, pitch AS_P)
    const int fr = ((lane >> 3) & 1) * 8 + (lane & 7);
    const int fc = (lane >> 4) * 4;
    const uint32_t a_lane_off = (uint32_t)((fr * AS_P + fc) * 4);
    uint32_t asAddr[2] = { smem_u32(As[0]) + (uint32_t)(wm * AS_P * 4) + a_lane_off,
                           smem_u32(As[1]) + (uint32_t)(wm * AS_P * 4) + a_lane_off };

    float acc[4][4][4];
#pragma unroll
    for (int mi = 0; mi < 4; mi++)
#pragma unroll
        for (int ni = 0; ni < 4; ni++)
#pragma unroll
            for (int r = 0; r < 4; r++) acc[mi][ni][r] = 0.f;

    const int nch = K / 16;

    {
        const float* Ab = A + (size_t)m0 * K;
        const float* Wb = W + n0;
#pragma unroll
        for (int i = 0; i < 2; i++) {
            int idx = t + i * 256;
            int ar = idx >> 2, as = idx & 3;
            float4 v = *(const float4*)(Ab + (size_t)ar * K + as * 4);
            float* d = As[0] + ar * AS_P + as * 4;
            d[0] = f2tf32(v.x); d[1] = f2tf32(v.y); d[2] = f2tf32(v.z); d[3] = f2tf32(v.w);
            int br = idx >> 5, bs = idx & 31;
            float4 w = *(const float4*)(Wb + (size_t)br * N + bs * 4);
            float* e = Bs[0] + br * BS_P + bs * 4;
            e[0] = f2tf32(w.x); e[1] = f2tf32(w.y); e[2] = f2tf32(w.z); e[3] = f2tf32(w.w);
        }
    }
    __syncthreads();

    for (int ch = 0; ch < nch; ch++) {
        const int s = ch & 1;

        float4 ra[2], rb[2];
        if (ch + 1 < nch) {
            const float* Ab = A + (size_t)m0 * K + (ch + 1) * 16;
            const float* Wb = W + (size_t)(ch + 1) * 16 * N + n0;
#pragma unroll
            for (int i = 0; i < 2; i++) {
                int idx = t + i * 256;
                ra[i] = *(const float4*)(Ab + (size_t)(idx >> 2) * K + (idx & 3) * 4);
                rb[i] = *(const float4*)(Wb + (size_t)(idx >> 5) * N + (idx & 31) * 4);
            }
        }

        const float* bs_ = Bs[s];
        const uint32_t af_base = asAddr[s];
#pragma unroll
        for (int ks = 0; ks < 2; ks++) {
            const int kk = ks * 8;
            uint32_t af[4][4], bf[4][2];
#pragma unroll
            for (int mi = 0; mi < 4; mi++)
                ldsm_x4(af[mi], af_base + (uint32_t)(mi * 16 * AS_P + kk) * 4);
#pragma unroll
            for (int ni = 0; ni < 4; ni++) {
                int cc = wn + ni * 8 + g;
                bf[ni][0] = __float_as_uint(bs_[(kk + t4) * BS_P + cc]);
                bf[ni][1] = __float_as_uint(bs_[(kk + t4 + 4) * BS_P + cc]);
            }
#pragma unroll
            for (int mi = 0; mi < 4; mi++)
#pragma unroll
                for (int ni = 0; ni < 4; ni++)
                    mma_tf32(acc[mi][ni], af[mi], bf[ni]);
        }

        if (ch + 1 < nch) {
            __syncthreads();
            const int sn = s ^ 1;
#pragma unroll
            for (int i = 0; i < 2; i++) {
                int idx = t + i * 256;
                int ar = idx >> 2, as = idx & 3;
                float* d = As[sn] + ar * AS_P + as * 4;
                d[0] = f2tf32(ra[i].x); d[1] = f2tf32(ra[i].y);
                d[2] = f2tf32(ra[i].z); d[3] = f2tf32(ra[i].w);
                int br = idx >> 5, bs = idx & 31;
                float* e = Bs[sn] + br * BS_P + bs * 4;
                e[0] = f2tf32(rb[i].x); e[1] = f2tf32(rb[i].y);
                e[2] = f2tf32(rb[i].z); e[3] = f2tf32(rb[i].w);
            }
            __syncthreads();
        }
    }

#pragma unroll
    for (int mi = 0; mi < 4; mi++) {
        int row = m0 + wm + mi * 16 + g;
#pragma unroll
        for (int ni = 0; ni < 4; ni++) {
            int col = n0 + wn + ni * 8 + 2 * t4;
            float2 bv = *(const float2*)(bias + col);
            float2 v0 = make_float2(acc[mi][ni][0] + bv.x, acc[mi][ni][1] + bv.y);
            float2 v1 = make_float2(acc[mi][ni][2] + bv.x, acc[mi][ni][3] + bv.y);
            *(float2*)(C + (size_t)row * N + col)       = v0;
            *(float2*)(C + (size_t)(row + 8) * N + col) = v1;
        }
    }
}

// ===========================================================================
// tf32 mma.sync flash attention, ldmatrix fragment loads.
// CTA: 8 warps, 128 queries, 64-key tiles; warp owns 16 full score rows.
// ===========================================================================
#define QS_OFF 0                    // [128][68]
#define KS_OFF (128*68)             // [64][68]   Ks[key][d]
#define VT_OFF (KS_OFF + 64*68)     // [64][68]   Vt[d][key]
#define PS_OFF (VT_OFF + 64*68)     // 8 x [16][68]
#define ATT_SMEM_FLOATS (PS_OFF + 8*16*68)
#define ATT_SMEM (ATT_SMEM_FLOATS * sizeof(float))   // 104448 B

__global__ __launch_bounds__(256, 2)
void attn_mma_kernel(const float* __restrict__ qkv, const float* __restrict__ mask,
                     float* __restrict__ att)
{
    extern __shared__ float smf[];
    float* Qs = smf + QS_OFF;
    float* Ks = smf + KS_OFF;
    float* Vt = smf + VT_OFF;

    const int t    = threadIdx.x;
    const int lane = t & 31;
    const int wid  = t >> 5;
    const int g    = lane >> 2;
    const int t4   = lane & 3;
    const int bh   = blockIdx.y;
    const int b    = bh / HEADS;
    const int h    = bh % HEADS;
    const int q0   = blockIdx.x * 128;

    float* Ps = smf + PS_OFF + wid * (16 * 68);

    // ldmatrix lane offsets (pitch 68 floats everywhere)
    const int fr = ((lane >> 3) & 1) * 8 + (lane & 7);     // A-frag row
    const int fc = (lane >> 4) * 4;                        // A-frag col
    const int br_ = (lane >> 4) * 8 + (lane & 7);          // B-frag row (x4 = 2 ni)
    const int bc_ = ((lane >> 3) & 1) * 4;                 // B-frag col
    const uint32_t smb   = smem_u32(smf);
    const uint32_t a_off = (uint32_t)((fr * 68 + fc) * 4);
    const uint32_t b_off = (uint32_t)((br_ * 68 + bc_) * 4);
    const uint32_t qfrag = smb + (uint32_t)((QS_OFF + wid * 16 * 68) * 4) + a_off;
    const uint32_t kfrag = smb + (uint32_t)(KS_OFF * 4) + b_off;
    const uint32_t vfrag = smb + (uint32_t)(VT_OFF * 4) + b_off;
    const uint32_t pfrag = smb + (uint32_t)((PS_OFF + wid * 16 * 68) * 4) + a_off;

    // ---- load Q tile [128][64], fold 1/8 scale, cvt tf32 ----
    {
        const float* qb = qkv + ((size_t)(b * SEQ + q0)) * QKV_N + h * (3 * HD);
#pragma unroll
        for (int i = 0; i < 8; i++) {
            int idx = t + i * 256;
            int row = idx >> 4, seg = idx & 15;
            float4 v = *(const float4*)(qb + (size_t)row * QKV_N + seg * 4);
            float* d = Qs + row * 68 + seg * 4;
            d[0] = f2tf32(v.x * 0.125f); d[1] = f2tf32(v.y * 0.125f);
            d[2] = f2tf32(v.z * 0.125f); d[3] = f2tf32(v.w * 0.125f);
        }
    }

    float m0 = -1e30f, m1 = -1e30f, l0 = 0.f, l1 = 0.f;
    float acc[8][4];
#pragma unroll
    for (int ni = 0; ni < 8; ni++)
#pragma unroll
        for (int r = 0; r < 4; r++) acc[ni][r] = 0.f;

    const int qrow = wid * 16 + g;

    for (int kt = 0; kt < SEQ / 64; kt++) {
        const int k0 = kt * 64;
        __syncthreads();

        // ---- K tile [64][64] -> Ks (tf32) ----
        {
            const float* kb = qkv + ((size_t)(b * SEQ + k0)) * QKV_N + h * (3 * HD) + HD;
#pragma unroll
            for (int i = 0; i < 4; i++) {
                int idx = t + i * 256;
                int row = idx >> 4, seg = idx & 15;
                float4 v = *(const float4*)(kb + (size_t)row * QKV_N + seg * 4);
                float* d = Ks + row * 68 + seg * 4;
                d[0] = f2tf32(v.x); d[1] = f2tf32(v.y); d[2] = f2tf32(v.z); d[3] = f2tf32(v.w);
            }
        }
        // ---- V tile [64][64] -> Vt[d][key] (4x4 register micro-transpose) ----
        {
            const int kg = t >> 4, ds = t & 15;
            const float* vb = qkv + ((size_t)(b * SEQ + k0 + kg * 4)) * QKV_N
                            + h * (3 * HD) + 2 * HD + ds * 4;
            float4 r0 = *(const float4*)(vb);
            float4 r1 = *(const float4*)(vb + QKV_N);
            float4 r2 = *(const float4*)(vb + 2 * QKV_N);
            float4 r3 = *(const float4*)(vb + 3 * QKV_N);
            float* d0 = Vt + (ds * 4 + 0) * 68 + kg * 4;
            float* d1 = Vt + (ds * 4 + 1) * 68 + kg * 4;
            float* d2 = Vt + (ds * 4 + 2) * 68 + kg * 4;
            float* d3 = Vt + (ds * 4 + 3) * 68 + kg * 4;
            *(float4*)d0 = make_float4(f2tf32(r0.x), f2tf32(r1.x), f2tf32(r2.x), f2tf32(r3.x));
            *(float4*)d1 = make_float4(f2tf32(r0.y), f2tf32(r1.y), f2tf32(r2.y), f2tf32(r3.y));
            *(float4*)d2 = make_float4(f2tf32(r0.z), f2tf32(r1.z), f2tf32(r2.z), f2tf32(r3.z));
            *(float4*)d3 = make_float4(f2tf32(r0.w), f2tf32(r1.w), f2tf32(r2.w), f2tf32(r3.w));
        }
        __syncthreads();

        // ---- scores = Q @ K^T ----
        float sc[8][4];
#pragma unroll
        for (int ni = 0; ni < 8; ni++)
#pragma unroll
            for (int r = 0; r < 4; r++) sc[ni][r] = 0.f;

#pragma unroll
        for (int kk = 0; kk < 64; kk += 8) {
            uint32_t af[4];
            ldsm_x4(af, qfrag + (uint32_t)(kk * 4));
#pragma unroll
            for (int nt = 0; nt < 4; nt++) {
                uint32_t bq[4];
                ldsm_x4(bq, kfrag + (uint32_t)((nt * 16 * 68 + kk) * 4));
                mma_tf32(sc[2 * nt],     af, &bq[0]);
                mma_tf32(sc[2 * nt + 1], af, &bq[2]);
            }
        }

        // ---- + mask, online softmax (rows g and g+8) ----
        {
            const float* mr0 = mask + (size_t)(q0 + qrow) * SEQ + k0 + 2 * t4;
            const float* mr1 = mr0 + 8 * SEQ;
            float mx0 = -1e30f, mx1 = -1e30f;
#pragma unroll
            for (int ni = 0; ni < 8; ni++) {
                float2 a = *(const float2*)(mr0 + 8 * ni);
                float2 c = *(const float2*)(mr1 + 8 * ni);
                sc[ni][0] += a.x; sc[ni][1] += a.y;
                sc[ni][2] += c.x; sc[ni][3] += c.y;
                mx0 = fmaxf(mx0, fmaxf(sc[ni][0], sc[ni][1]));
                mx1 = fmaxf(mx1, fmaxf(sc[ni][2], sc[ni][3]));
            }
#pragma unroll
            for (int off = 1; off <= 2; off <<= 1) {
                mx0 = fmaxf(mx0, __shfl_xor_sync(0xffffffffu, mx0, off));
                mx1 = fmaxf(mx1, __shfl_xor_sync(0xffffffffu, mx1, off));
            }
            float mn0 = fmaxf(m0, mx0), mn1 = fmaxf(m1, mx1);
            float c0 = __expf(m0 - mn0), c1 = __expf(m1 - mn1);
            float rs0 = 0.f, rs1 = 0.f;
            float* p0 = Ps + g * 68 + 2 * t4;
            float* p1 = Ps + (g + 8) * 68 + 2 * t4;
#pragma unroll
            for (int ni = 0; ni < 8; ni++) {
                float e00 = f2tf32(__expf(sc[ni][0] - mn0));
                float e01 = f2tf32(__expf(sc[ni][1] - mn0));
                float e10 = f2tf32(__expf(sc[ni][2] - mn1));
                float e11 = f2tf32(__expf(sc[ni][3] - mn1));
                rs0 += e00 + e01; rs1 += e10 + e11;
                *(float2*)(p0 + 8 * ni) = make_float2(e00, e01);
                *(float2*)(p1 + 8 * ni) = make_float2(e10, e11);
            }
#pragma unroll
            for (int off = 1; off <= 2; off <<= 1) {
                rs0 += __shfl_xor_sync(0xffffffffu, rs0, off);
                rs1 += __shfl_xor_sync(0xffffffffu, rs1, off);
            }
            l0 = l0 * c0 + rs0; l1 = l1 * c1 + rs1;
            m0 = mn0; m1 = mn1;
#pragma unroll
            for (int ni = 0; ni < 8; ni++) {
                acc[ni][0] *= c0; acc[ni][1] *= c0;
                acc[ni][2] *= c1; acc[ni][3] *= c1;
            }
        }
        __syncwarp();

        // ---- acc += P @ V ----
#pragma unroll
        for (int kk = 0; kk < 64; kk += 8) {
            uint32_t af[4];
            ldsm_x4(af, pfrag + (uint32_t)(kk * 4));
#pragma unroll
            for (int nt = 0; nt < 4; nt++) {
                uint32_t bv[4];
                ldsm_x4(bv, vfrag + (uint32_t)((nt * 16 * 68 + kk) * 4));
                mma_tf32(acc[2 * nt],     af, &bv[0]);
                mma_tf32(acc[2 * nt + 1], af, &bv[2]);
            }
        }
    }

    // ---- normalize + store ----
    {
        float inv0 = 1.f / l0, inv1 = 1.f / l1;
        float* o0 = att + (size_t)(b * SEQ + q0 + qrow) * DMODEL + h * HD + 2 * t4;
        float* o1 = o0 + 8 * DMODEL;
#pragma unroll
        for (int ni = 0; ni < 8; ni++) {
            *(float2*)(o0 + 8 * ni) = make_float2(acc[ni][0] * inv0, acc[ni][1] * inv0);
            *(float2*)(o1 + 8 * ni) = make_float2(acc[ni][2] * inv1, acc[ni][3] * inv1);
        }
    }
}

// ---------------------------------------------------------------------------
extern "C" void kernel_launch(void* const* d_in, const int* in_sizes, int n_in,
                              void* d_out, int out_size)
{
    const float* x     = (const float*)d_in[0];
    const float* mask  = (const float*)d_in[1];
    const float* w_qkv = (const float*)d_in[2];
    const float* b_qkv = (const float*)d_in[3];
    const float* w_out = (const float*)d_in[4];
    const float* b_out = (const float*)d_in[5];
    float* out = (float*)d_out;

    float* qkv; cudaGetSymbolAddress((void**)&qkv, g_qkv);
    float* att; cudaGetSymbolAddress((void**)&att, g_att);

    cudaFuncSetAttribute(gemm_mma_kernel, cudaFuncAttributeMaxDynamicSharedMemorySize,
                         (int)GEMM_SMEM);
    cudaFuncSetAttribute(attn_mma_kernel, cudaFuncAttributeMaxDynamicSharedMemorySize,
                         (int)ATT_SMEM);

    // 1) QKV projection (tf32 mma + ldmatrix)
    {
        dim3 grid(QKV_N / 128, MROWS / 128);
        gemm_mma_kernel<<<grid, 256, GEMM_SMEM>>>(x, w_qkv, b_qkv, qkv, QKV_N, DMODEL);
    }
    // 2) attention (tf32 mma flash + ldmatrix)
    {
        dim3 grid(SEQ / 128, BATCH * HEADS);
        attn_mma_kernel<<<grid, 256, ATT_SMEM>>>(qkv, mask, att);
    }
    // 3) output projection (tf32 mma + ldmatrix)
    {
        dim3 grid(DMODEL / 128, MROWS / 128);
        gemm_mma_kernel<<<grid, 256, GEMM_SMEM>>>(att, w_out, b_out, out, DMODEL, DMODEL);
    }
}

// round 6
// speedup vs baseline: 1.5913x; 1.5913x over previous
#include <cuda_runtime.h>
#include <math.h>
#include <stdint.h>

#define BATCH 2
#define SEQ   2048
#define DMODEL 1024
#define HEADS 16
#define HD    64
#define QKV_N (3*DMODEL)       // 3072
#define MROWS (BATCH*SEQ)      // 4096

__device__ float g_qkv[(size_t)MROWS * QKV_N];    // [B*S, 3072]
__device__ float g_att[(size_t)MROWS * DMODEL];   // [B*S, 1024]

// ===========================================================================
// helpers
// ===========================================================================
__device__ __forceinline__ float f2tf32(float f) {
    uint32_t r;
    asm("cvt.rna.tf32.f32 %0, %1;" : "=r"(r) : "f"(f));
    return __uint_as_float(r);
}
__device__ __forceinline__ uint32_t tf32bits(float f) {
    uint32_t r;
    asm("cvt.rna.tf32.f32 %0, %1;" : "=r"(r) : "f"(f));
    return r;
}
__device__ __forceinline__ uint32_t smem_u32(const void* p) {
    uint32_t a;
    asm("{ .reg .u64 t; cvta.to.shared.u64 t, %1; cvt.u32.u64 %0, t; }" : "=r"(a) : "l"(p));
    return a;
}
__device__ __forceinline__ void mma_tf32(float c[4], const uint32_t a[4], const uint32_t b[2]) {
    asm volatile(
        "mma.sync.aligned.m16n8k8.row.col.f32.tf32.tf32.f32 "
        "{%0,%1,%2,%3}, {%4,%5,%6,%7}, {%8,%9}, {%0,%1,%2,%3};"
        : "+f"(c[0]), "+f"(c[1]), "+f"(c[2]), "+f"(c[3])
        : "r"(a[0]), "r"(a[1]), "r"(a[2]), "r"(a[3]), "r"(b[0]), "r"(b[1]));
}
__device__ __forceinline__ void cp_async16(uint32_t saddr, const void* gptr) {
    asm volatile("cp.async.ca.shared.global [%0], [%1], 16;" :: "r"(saddr), "l"(gptr));
}
__device__ __forceinline__ void cp_commit() {
    asm volatile("cp.async.commit_group;" ::: "memory");
}
__device__ __forceinline__ void cp_wait2() {
    asm volatile("cp.async.wait_group 2;" ::: "memory");
}

// ===========================================================================
// tf32 mma.sync GEMM + bias, 4-stage cp.async pipeline.
// C[M,N] = A[M,K] @ W[K,N] + bias[N]. 128x128 CTA, BK=16, 8 warps (64x32).
// Smem holds raw fp32; cvt.rna applied at fragment-load time (same numerics
// as converting at store time).
// ===========================================================================
#define AS_P 20
#define BS_P 136
#define AS_FLOATS (128 * AS_P)          // 2560
#define BS_FLOATS (16 * BS_P)           // 2176
#define ST_FLOATS (AS_FLOATS + BS_FLOATS)
#define NSTAGE 4
#define GEMM_SMEM (NSTAGE * ST_FLOATS * sizeof(float))   // 75776

__global__ __launch_bounds__(256, 2)
void gemm_mma_kernel(const float* __restrict__ A, const float* __restrict__ W,
                     const float* __restrict__ bias, float* __restrict__ C,
                     int N, int K)
{
    extern __shared__ float smf[];
    const uint32_t smb = smem_u32(smf);

    const int t    = threadIdx.x;
    const int lane = t & 31;
    const int wid  = t >> 5;
    const int wm   = (wid >> 2) * 64;
    const int wn   = (wid & 3) * 32;
    const int g    = lane >> 2;
    const int t4   = lane & 3;
    const int m0   = blockIdx.y * 128;
    const int n0   = blockIdx.x * 128;

    // per-thread fill offsets
    const int ar = t >> 1;                    // A row 0..127 (2 segs/thread)
    const int as0 = (t & 1) * 2;              // A segs as0, as0+1 of 4
    const int br = t >> 4;                    // B row 0..15 (2 segs/thread)
    const int bs0 = (t & 15) * 2;             // B segs bs0, bs0+1 of 32

    float acc[4][4][4];
#pragma unroll
    for (int mi = 0; mi < 4; mi++)
#pragma unroll
        for (int ni = 0; ni < 4; ni++)
#pragma unroll
            for (int r = 0; r < 4; r++) acc[mi][ni][r] = 0.f;

    const int nch = K / 16;   // 64

    // issue loads for chunk c into stage s
    auto load_chunk = [&](int c, int s) {
        const uint32_t stA = smb + (uint32_t)(s * ST_FLOATS) * 4u;
        const uint32_t stB = stA + (uint32_t)AS_FLOATS * 4u;
        const float* Ab = A + (size_t)(m0 + ar) * K + c * 16 + as0 * 4;
        cp_async16(stA + (uint32_t)(ar * AS_P + as0 * 4) * 4u, Ab);
        cp_async16(stA + (uint32_t)(ar * AS_P + (as0 + 1) * 4) * 4u, Ab + 4);
        const float* Wb = W + (size_t)(c * 16 + br) * N + n0 + bs0 * 4;
        cp_async16(stB + (uint32_t)(br * BS_P + bs0 * 4) * 4u, Wb);
        cp_async16(stB + (uint32_t)(br * BS_P + (bs0 + 1) * 4) * 4u, Wb + 4);
    };

    // prologue: stages 0..2
#pragma unroll
    for (int c = 0; c < NSTAGE - 1; c++) { load_chunk(c, c); cp_commit(); }

    for (int c = 0; c < nch; c++) {
        cp_wait2();
        __syncthreads();

        // refill the stage freed by chunk c-1 (all warps are past it)
        if (c + NSTAGE - 1 < nch) load_chunk(c + NSTAGE - 1, (c + NSTAGE - 1) & (NSTAGE - 1));
        cp_commit();

        const int s = c & (NSTAGE - 1);
        const float* as_ = smf + s * ST_FLOATS;
        const float* bs_ = as_ + AS_FLOATS;

#pragma unroll
        for (int ks = 0; ks < 2; ks++) {
            const int kk = ks * 8;
            uint32_t af[4][4], bf[4][2];
#pragma unroll
            for (int mi = 0; mi < 4; mi++) {
                int r0 = wm + mi * 16 + g;
                af[mi][0] = tf32bits(as_[r0 * AS_P + kk + t4]);
                af[mi][1] = tf32bits(as_[(r0 + 8) * AS_P + kk + t4]);
                af[mi][2] = tf32bits(as_[r0 * AS_P + kk + t4 + 4]);
                af[mi][3] = tf32bits(as_[(r0 + 8) * AS_P + kk + t4 + 4]);
            }
#pragma unroll
            for (int ni = 0; ni < 4; ni++) {
                int cc = wn + ni * 8 + g;
                bf[ni][0] = tf32bits(bs_[(kk + t4) * BS_P + cc]);
                bf[ni][1] = tf32bits(bs_[(kk + t4 + 4) * BS_P + cc]);
            }
#pragma unroll
            for (int mi = 0; mi < 4; mi++)
#pragma unroll
                for (int ni = 0; ni < 4; ni++)
                    mma_tf32(acc[mi][ni], af[mi], bf[ni]);
        }
    }

#pragma unroll
    for (int mi = 0; mi < 4; mi++) {
        int row = m0 + wm + mi * 16 + g;
#pragma unroll
        for (int ni = 0; ni < 4; ni++) {
            int col = n0 + wn + ni * 8 + 2 * t4;
            float2 bv = *(const float2*)(bias + col);
            float2 v0 = make_float2(acc[mi][ni][0] + bv.x, acc[mi][ni][1] + bv.y);
            float2 v1 = make_float2(acc[mi][ni][2] + bv.x, acc[mi][ni][3] + bv.y);
            *(float2*)(C + (size_t)row * N + col)       = v0;
            *(float2*)(C + (size_t)(row + 8) * N + col) = v1;
        }
    }
}

// ===========================================================================
// tf32 mma.sync flash attention — EXACT R4 version (known-good, 430us).
// ===========================================================================
#define QS_OFF 0                    // [128][68]
#define KS_OFF (128*68)             // [64][68]
#define VT_OFF (KS_OFF + 64*68)     // [64][68]  Vt[d][key]
#define PS_OFF (VT_OFF + 64*68)     // 8 x [16][68]
#define ATT_SMEM_FLOATS (PS_OFF + 8*16*68)
#define ATT_SMEM (ATT_SMEM_FLOATS * sizeof(float))   // 104448 B

__global__ __launch_bounds__(256, 2)
void attn_mma_kernel(const float* __restrict__ qkv, const float* __restrict__ mask,
                     float* __restrict__ att)
{
    extern __shared__ float smf[];
    float* Qs = smf + QS_OFF;
    float* Ks = smf + KS_OFF;
    float* Vt = smf + VT_OFF;

    const int t    = threadIdx.x;
    const int lane = t & 31;
    const int wid  = t >> 5;
    const int g    = lane >> 2;
    const int t4   = lane & 3;
    const int bh   = blockIdx.y;
    const int b    = bh / HEADS;
    const int h    = bh % HEADS;
    const int q0   = blockIdx.x * 128;

    float* Ps = smf + PS_OFF + wid * (16 * 68);

    {
        const float* qb = qkv + ((size_t)(b * SEQ + q0)) * QKV_N + h * (3 * HD);
#pragma unroll
        for (int i = 0; i < 8; i++) {
            int idx = t + i * 256;
            int row = idx >> 4, seg = idx & 15;
            float4 v = *(const float4*)(qb + (size_t)row * QKV_N + seg * 4);
            float* d = Qs + row * 68 + seg * 4;
            d[0] = f2tf32(v.x * 0.125f); d[1] = f2tf32(v.y * 0.125f);
            d[2] = f2tf32(v.z * 0.125f); d[3] = f2tf32(v.w * 0.125f);
        }
    }

    float m0 = -1e30f, m1 = -1e30f, l0 = 0.f, l1 = 0.f;
    float acc[8][4];
#pragma unroll
    for (int ni = 0; ni < 8; ni++)
#pragma unroll
        for (int r = 0; r < 4; r++) acc[ni][r] = 0.f;

    const int qrow = wid * 16 + g;
    const float* qsw = Qs + qrow * 68;

    for (int kt = 0; kt < SEQ / 64; kt++) {
        const int k0 = kt * 64;
        __syncthreads();

        {
            const float* kb = qkv + ((size_t)(b * SEQ + k0)) * QKV_N + h * (3 * HD) + HD;
#pragma unroll
            for (int i = 0; i < 4; i++) {
                int idx = t + i * 256;
                int row = idx >> 4, seg = idx & 15;
                float4 v = *(const float4*)(kb + (size_t)row * QKV_N + seg * 4);
                float* d = Ks + row * 68 + seg * 4;
                d[0] = f2tf32(v.x); d[1] = f2tf32(v.y); d[2] = f2tf32(v.z); d[3] = f2tf32(v.w);
            }
        }
        {
            const int kg = t >> 4, ds = t & 15;
            const float* vb = qkv + ((size_t)(b * SEQ + k0 + kg * 4)) * QKV_N
                            + h * (3 * HD) + 2 * HD + ds * 4;
            float4 r0 = *(const float4*)(vb);
            float4 r1 = *(const float4*)(vb + QKV_N);
            float4 r2 = *(const float4*)(vb + 2 * QKV_N);
            float4 r3 = *(const float4*)(vb + 3 * QKV_N);
            float* d0 = Vt + (ds * 4 + 0) * 68 + kg * 4;
            float* d1 = Vt + (ds * 4 + 1) * 68 + kg * 4;
            float* d2 = Vt + (ds * 4 + 2) * 68 + kg * 4;
            float* d3 = Vt + (ds * 4 + 3) * 68 + kg * 4;
            *(float4*)d0 = make_float4(f2tf32(r0.x), f2tf32(r1.x), f2tf32(r2.x), f2tf32(r3.x));
            *(float4*)d1 = make_float4(f2tf32(r0.y), f2tf32(r1.y), f2tf32(r2.y), f2tf32(r3.y));
            *(float4*)d2 = make_float4(f2tf32(r0.z), f2tf32(r1.z), f2tf32(r2.z), f2tf32(r3.z));
            *(float4*)d3 = make_float4(f2tf32(r0.w), f2tf32(r1.w), f2tf32(r2.w), f2tf32(r3.w));
        }
        __syncthreads();

        float sc[8][4];
#pragma unroll
        for (int ni = 0; ni < 8; ni++)
#pragma unroll
            for (int r = 0; r < 4; r++) sc[ni][r] = 0.f;

#pragma unroll
        for (int kk = 0; kk < 64; kk += 8) {
            uint32_t af[4];
            af[0] = __float_as_uint(qsw[kk + t4]);
            af[1] = __float_as_uint(qsw[8 * 68 + kk + t4]);
            af[2] = __float_as_uint(qsw[kk + t4 + 4]);
            af[3] = __float_as_uint(qsw[8 * 68 + kk + t4 + 4]);
#pragma unroll
            for (int ni = 0; ni < 8; ni++) {
                uint32_t bf[2];
                bf[0] = __float_as_uint(Ks[(ni * 8 + g) * 68 + kk + t4]);
                bf[1] = __float_as_uint(Ks[(ni * 8 + g) * 68 + kk + t4 + 4]);
                mma_tf32(sc[ni], af, bf);
            }
        }

        {
            const float* mr0 = mask + (size_t)(q0 + qrow) * SEQ + k0 + 2 * t4;
            const float* mr1 = mr0 + 8 * SEQ;
            float mx0 = -1e30f, mx1 = -1e30f;
#pragma unroll
            for (int ni = 0; ni < 8; ni++) {
                float2 a = *(const float2*)(mr0 + 8 * ni);
                float2 c = *(const float2*)(mr1 + 8 * ni);
                sc[ni][0] += a.x; sc[ni][1] += a.y;
                sc[ni][2] += c.x; sc[ni][3] += c.y;
                mx0 = fmaxf(mx0, fmaxf(sc[ni][0], sc[ni][1]));
                mx1 = fmaxf(mx1, fmaxf(sc[ni][2], sc[ni][3]));
            }
#pragma unroll
            for (int off = 1; off <= 2; off <<= 1) {
                mx0 = fmaxf(mx0, __shfl_xor_sync(0xffffffffu, mx0, off));
                mx1 = fmaxf(mx1, __shfl_xor_sync(0xffffffffu, mx1, off));
            }
            float mn0 = fmaxf(m0, mx0), mn1 = fmaxf(m1, mx1);
            float c0 = __expf(m0 - mn0), c1 = __expf(m1 - mn1);
            float rs0 = 0.f, rs1 = 0.f;
            float* p0 = Ps + g * 68 + 2 * t4;
            float* p1 = Ps + (g + 8) * 68 + 2 * t4;
#pragma unroll
            for (int ni = 0; ni < 8; ni++) {
                float e00 = f2tf32(__expf(sc[ni][0] - mn0));
                float e01 = f2tf32(__expf(sc[ni][1] - mn0));
                float e10 = f2tf32(__expf(sc[ni][2] - mn1));
                float e11 = f2tf32(__expf(sc[ni][3] - mn1));
                rs0 += e00 + e01; rs1 += e10 + e11;
                *(float2*)(p0 + 8 * ni) = make_float2(e00, e01);
                *(float2*)(p1 + 8 * ni) = make_float2(e10, e11);
            }
#pragma unroll
            for (int off = 1; off <= 2; off <<= 1) {
                rs0 += __shfl_xor_sync(0xffffffffu, rs0, off);
                rs1 += __shfl_xor_sync(0xffffffffu, rs1, off);
            }
            l0 = l0 * c0 + rs0; l1 = l1 * c1 + rs1;
            m0 = mn0; m1 = mn1;
#pragma unroll
            for (int ni = 0; ni < 8; ni++) {
                acc[ni][0] *= c0; acc[ni][1] *= c0;
                acc[ni][2] *= c1; acc[ni][3] *= c1;
            }
        }
        __syncwarp();

#pragma unroll
        for (int kk = 0; kk < 64; kk += 8) {
            uint32_t af[4];
            af[0] = __float_as_uint(Ps[g * 68 + kk + t4]);
            af[1] = __float_as_uint(Ps[(g + 8) * 68 + kk + t4]);
            af[2] = __float_as_uint(Ps[g * 68 + kk + t4 + 4]);
            af[3] = __float_as_uint(Ps[(g + 8) * 68 + kk + t4 + 4]);
#pragma unroll
            for (int ni = 0; ni < 8; ni++) {
                uint32_t bf[2];
                bf[0] = __float_as_uint(Vt[(ni * 8 + g) * 68 + kk + t4]);
                bf[1] = __float_as_uint(Vt[(ni * 8 + g) * 68 + kk + t4 + 4]);
                mma_tf32(acc[ni], af, bf);
            }
        }
    }

    {
        float inv0 = 1.f / l0, inv1 = 1.f / l1;
        float* o0 = att + (size_t)(b * SEQ + q0 + qrow) * DMODEL + h * HD + 2 * t4;
        float* o1 = o0 + 8 * DMODEL;
#pragma unroll
        for (int ni = 0; ni < 8; ni++) {
            *(float2*)(o0 + 8 * ni) = make_float2(acc[ni][0] * inv0, acc[ni][1] * inv0);
            *(float2*)(o1 + 8 * ni) = make_float2(acc[ni][2] * inv1, acc[ni][3] * inv1);
        }
    }
}

// ---------------------------------------------------------------------------
extern "C" void kernel_launch(void* const* d_in, const int* in_sizes, int n_in,
                              void* d_out, int out_size)
{
    const float* x     = (const float*)d_in[0];
    const float* mask  = (const float*)d_in[1];
    const float* w_qkv = (const float*)d_in[2];
    const float* b_qkv = (const float*)d_in[3];
    const float* w_out = (const float*)d_in[4];
    const float* b_out = (const float*)d_in[5];
    float* out = (float*)d_out;

    float* qkv; cudaGetSymbolAddress((void**)&qkv, g_qkv);
    float* att; cudaGetSymbolAddress((void**)&att, g_att);

    cudaFuncSetAttribute(gemm_mma_kernel, cudaFuncAttributeMaxDynamicSharedMemorySize,
                         (int)GEMM_SMEM);
    cudaFuncSetAttribute(attn_mma_kernel, cudaFuncAttributeMaxDynamicSharedMemorySize,
                         (int)ATT_SMEM);

    // 1) QKV projection (tf32 mma + cp.async pipeline)
    {
        dim3 grid(QKV_N / 128, MROWS / 128);
        gemm_mma_kernel<<<grid, 256, GEMM_SMEM>>>(x, w_qkv, b_qkv, qkv, QKV_N, DMODEL);
    }
    // 2) attention (tf32 mma flash, R4 scalar-LDS fragments)
    {
        dim3 grid(SEQ / 128, BATCH * HEADS);
        attn_mma_kernel<<<grid, 256, ATT_SMEM>>>(qkv, mask, att);
    }
    // 3) output projection (tf32 mma + cp.async pipeline)
    {
        dim3 grid(DMODEL / 128, MROWS / 128);
        gemm_mma_kernel<<<grid, 256, GEMM_SMEM>>>(att, w_out, b_out, out, DMODEL, DMODEL);
    }
}